// round 7
// baseline (speedup 1.0000x reference)
#include <cuda_runtime.h>
#include <cuda_bf16.h>
#include <cuda_fp8.h>
#include <math.h>
#include <cstdint>

#define B_      2
#define F_      16
#define H_      32
#define W_      32
#define HW      1024
#define NFRM    32
#define C_      320
#define CEXP    512
#define D_INNER 1024
#define NHEADS  16
#define HEADDIM 64
#define D_STATE 128
#define D_CONV  4
#define CONV_DIM 1280
#define D_IN_PROJ 2320
#define GROUPS  32
#define NSEQ    2048
#define L_      16
#define NTOK    32768

#define NP2320  2432
#define NPF     384
#define YSCALE  32.0f

// ---------------- scratch ---------------------------------------------------
__device__ __nv_bfloat16 g_a0[(size_t)NTOK*C_];
__device__ __nv_bfloat16 g_a2[(size_t)NTOK*CEXP];
__device__ uint8_t       g_a28[(size_t)NTOK*CEXP];
__device__ __nv_bfloat16 g_zxb[(size_t)NTOK*D_IN_PROJ];
__device__ uint8_t       g_yb8[(size_t)NTOK*D_INNER];
__device__ __nv_bfloat16 g_o1[(size_t)NTOK*CEXP];
__device__ float         g_c2[(size_t)NTOK*C_];
__device__ float         g_gst[NFRM*GROUPS*2];
__device__ __nv_bfloat16 g_w21[CEXP*C_];
__device__ __nv_bfloat16 g_wf[(size_t)NPF*CEXP];
__device__ float         g_b21[CEXP];
__device__ float         g_bf[C_];
__device__ uint8_t       g_wi8[(size_t)NP2320*CEXP];
__device__ uint8_t       g_wo8[(size_t)CEXP*D_INNER];
__device__ unsigned      g_amax[4];   // 0: in_proj_w, 1: wo*rms, 2: a2

// ---------------- PTX helpers ----------------------------------------------
__device__ __forceinline__ uint32_t smem_u32(const void* p) {
    uint32_t a;
    asm("{ .reg .u64 t; cvta.to.shared.u64 t, %1; cvt.u32.u64 %0, t; }" : "=r"(a) : "l"(p));
    return a;
}
__device__ __forceinline__ void cp16(uint32_t dst, const void* src) {
    asm volatile("cp.async.cg.shared.global [%0], [%1], 16;" :: "r"(dst), "l"(src) : "memory");
}
__device__ __forceinline__ void ldmx4(uint32_t addr, uint32_t& r0, uint32_t& r1,
                                      uint32_t& r2, uint32_t& r3) {
    asm volatile("ldmatrix.sync.aligned.m8n8.x4.shared.b16 {%0,%1,%2,%3}, [%4];"
                 : "=r"(r0), "=r"(r1), "=r"(r2), "=r"(r3) : "r"(addr));
}
__device__ __forceinline__ void mma16816(float* c, const uint32_t* a, const uint32_t* b) {
    asm volatile("mma.sync.aligned.m16n8k16.row.col.f32.bf16.bf16.f32 "
                 "{%0,%1,%2,%3}, {%4,%5,%6,%7}, {%8,%9}, {%0,%1,%2,%3};"
                 : "+f"(c[0]), "+f"(c[1]), "+f"(c[2]), "+f"(c[3])
                 : "r"(a[0]), "r"(a[1]), "r"(a[2]), "r"(a[3]), "r"(b[0]), "r"(b[1]));
}
__device__ __forceinline__ void mma16832f8(float* c, const uint32_t* a, const uint32_t* b) {
    asm volatile("mma.sync.aligned.m16n8k32.row.col.f32.e4m3.e4m3.f32 "
                 "{%0,%1,%2,%3}, {%4,%5,%6,%7}, {%8,%9}, {%0,%1,%2,%3};"
                 : "+f"(c[0]), "+f"(c[1]), "+f"(c[2]), "+f"(c[3])
                 : "r"(a[0]), "r"(a[1]), "r"(a[2]), "r"(a[3]), "r"(b[0]), "r"(b[1]));
}
__device__ __forceinline__ void storev(float* p, float v)         { *p = v; }
__device__ __forceinline__ void storev(__nv_bfloat16* p, float v) { *p = __float2bfloat16(v); }
__device__ __forceinline__ uint8_t to_fp8(float v) {
    __nv_fp8_e4m3 q(v);
    return *reinterpret_cast<uint8_t*>(&q);
}
__device__ __forceinline__ float scale_from(const unsigned* am) {
    float m = __uint_as_float(*am);
    return (m > 0.f) ? 439.f / m : 1.f;
}

// row remap for fused permutes
template<int PERM> __device__ __forceinline__ int rowmap(int r) {
    if (PERM == 1) {            // dest seq-order, src frame-order
        int f = r & 15, hw = (r >> 4) & 1023, bb = r >> 14;
        return bb * 16384 + f * 1024 + hw;
    } else if (PERM == 2) {     // dest frame-order, src seq-order
        int hw = r & 1023, f = (r >> 10) & 15, bb = r >> 14;
        return bb * 16384 + hw * 16 + f;
    }
    return r;
}

// ---------------- bf16 HMMA GEMM (128x128x64, 3-stage) -----------------------
#define GEMM_SMEM (3*2*18432)   // 110592
template<typename OutT, int PERM>
__global__ void __launch_bounds__(256, 2)
tc_gemm(const __nv_bfloat16* __restrict__ A, const __nv_bfloat16* __restrict__ B,
        const float* __restrict__ bias, OutT* __restrict__ C, int M, int N, int K)
{
    extern __shared__ char smraw[];
    const uint32_t sbase = smem_u32(smraw);
    const int tid = threadIdx.x;
    const int lane = tid & 31, warp = tid >> 5;
    const int wm = (warp & 3) * 32, wn = (warp >> 2) * 64;
    const int m0 = blockIdx.y * 128, n0 = blockIdx.x * 128;

    const int seg = tid & 7, r0 = tid >> 3;
    int arows[4];
    #pragma unroll
    for (int j = 0; j < 4; ++j) arows[j] = rowmap<PERM>(m0 + r0 + j * 32);

    float acc[2][8][4];
    #pragma unroll
    for (int i = 0; i < 2; ++i)
        #pragma unroll
        for (int j = 0; j < 8; ++j)
            #pragma unroll
            for (int k = 0; k < 4; ++k) acc[i][j][k] = 0.f;

    const int nc = K >> 6;
    auto load = [&](int i) {
        const uint32_t da = sbase + (uint32_t)(i % 3) * 36864u;
        const uint32_t db = da + 18432u;
        const int k0 = i << 6;
        #pragma unroll
        for (int j = 0; j < 4; ++j) {
            int row = r0 + j * 32;
            uint32_t off = (uint32_t)row * 144u + (uint32_t)seg * 16u;
            cp16(da + off, A + (size_t)arows[j] * K + k0 + seg * 8);
            cp16(db + off, B + (size_t)(n0 + row) * K + k0 + seg * 8);
        }
        asm volatile("cp.async.commit_group;" ::: "memory");
    };

    load(0);
    if (nc > 1) load(1);

    for (int i = 0; i < nc; ++i) {
        if (i + 1 < nc) asm volatile("cp.async.wait_group 1;" ::: "memory");
        else            asm volatile("cp.async.wait_group 0;" ::: "memory");
        __syncthreads();
        if (i + 2 < nc) load(i + 2);

        const uint32_t sA  = sbase + (uint32_t)(i % 3) * 36864u;
        const uint32_t sBt = sA + 18432u;
        #pragma unroll
        for (int ks = 0; ks < 64; ks += 16) {
            uint32_t af[2][4];
            #pragma unroll
            for (int mt = 0; mt < 2; ++mt) {
                uint32_t addr = sA
                    + (uint32_t)(wm + mt * 16 + (lane & 15)) * 144u
                    + (uint32_t)(ks + ((lane >> 4) << 3)) * 2u;
                ldmx4(addr, af[mt][0], af[mt][1], af[mt][2], af[mt][3]);
            }
            uint32_t bf[8][2];
            #pragma unroll
            for (int nt2 = 0; nt2 < 4; ++nt2) {
                int n  = wn + nt2 * 16 + (lane & 7) + ((lane >> 4) << 3);
                int kk = ks + (((lane >> 3) & 1) << 3);
                uint32_t addr = sBt + (uint32_t)n * 144u + (uint32_t)kk * 2u;
                ldmx4(addr, bf[nt2*2][0], bf[nt2*2][1], bf[nt2*2+1][0], bf[nt2*2+1][1]);
            }
            #pragma unroll
            for (int mt = 0; mt < 2; ++mt)
                #pragma unroll
                for (int nt = 0; nt < 8; ++nt)
                    mma16816(acc[mt][nt], af[mt], bf[nt]);
        }
    }

    #pragma unroll
    for (int mt = 0; mt < 2; ++mt) {
        int row = m0 + wm + mt * 16 + (lane >> 2);
        #pragma unroll
        for (int nt = 0; nt < 8; ++nt) {
            int col = n0 + wn + nt * 8 + (lane & 3) * 2;
            if (col < N) {
                float b0 = bias ? bias[col]     : 0.f;
                float b1 = bias ? bias[col + 1] : 0.f;
                storev(C + (size_t)row * N + col,           acc[mt][nt][0] + b0);
                storev(C + (size_t)row * N + col + 1,       acc[mt][nt][1] + b1);
                storev(C + (size_t)(row + 8) * N + col,     acc[mt][nt][2] + b0);
                storev(C + (size_t)(row + 8) * N + col + 1, acc[mt][nt][3] + b1);
            }
        }
    }
}

// ---------------- fp8 QMMA GEMM: C = A[perm] @ B^T, scaled -------------------
// A [M,K] e4m3, B [N,K] e4m3. 128x128x64(bytes) tile, 3-stage ring.
// 80-byte SMEM stride; fragment layouts identical byte-wise to bf16 ldmatrix.
// out = acc / (sa*sw) (+bias). sa from amA (or fixA if amA null), sw from amW.
#define GEMM8_SMEM (3*2*10240)  // 61440
template<typename OutT, int PERM>
__global__ void __launch_bounds__(256, 2)
tc_gemm8(const uint8_t* __restrict__ A, const uint8_t* __restrict__ B,
         const unsigned* __restrict__ amA, float fixA,
         const unsigned* __restrict__ amW,
         const float* __restrict__ bias, OutT* __restrict__ C, int M, int N, int K)
{
    extern __shared__ char smraw[];
    const uint32_t sbase = smem_u32(smraw);
    const int tid = threadIdx.x;
    const int lane = tid & 31, warp = tid >> 5;
    const int wm = (warp & 3) * 32, wn = (warp >> 2) * 64;
    const int m0 = blockIdx.y * 128, n0 = blockIdx.x * 128;

    const int seg = tid & 3, r0 = tid >> 2;     // 64 rows x 4 16B-segs
    int arows[2];
    arows[0] = rowmap<PERM>(m0 + r0);
    arows[1] = rowmap<PERM>(m0 + 64 + r0);

    float acc[2][8][4];
    #pragma unroll
    for (int i = 0; i < 2; ++i)
        #pragma unroll
        for (int j = 0; j < 8; ++j)
            #pragma unroll
            for (int k = 0; k < 4; ++k) acc[i][j][k] = 0.f;

    const int nc = K >> 6;                       // 64 bytes per iter
    auto load = [&](int i) {
        const uint32_t da = sbase + (uint32_t)(i % 3) * 20480u;
        const uint32_t db = da + 10240u;
        const int k0 = i << 6;
        #pragma unroll
        for (int j = 0; j < 2; ++j) {
            int row = r0 + j * 64;
            uint32_t off = (uint32_t)row * 80u + (uint32_t)seg * 16u;
            cp16(da + off, A + (size_t)arows[j] * K + k0 + seg * 16);
            cp16(db + off, B + (size_t)(n0 + row) * K + k0 + seg * 16);
        }
        asm volatile("cp.async.commit_group;" ::: "memory");
    };

    load(0);
    if (nc > 1) load(1);

    for (int i = 0; i < nc; ++i) {
        if (i + 1 < nc) asm volatile("cp.async.wait_group 1;" ::: "memory");
        else            asm volatile("cp.async.wait_group 0;" ::: "memory");
        __syncthreads();
        if (i + 2 < nc) load(i + 2);

        const uint32_t sA  = sbase + (uint32_t)(i % 3) * 20480u;
        const uint32_t sBt = sA + 10240u;
        #pragma unroll
        for (int ks = 0; ks < 64; ks += 32) {    // 32 k-bytes per mma step
            uint32_t af[2][4];
            #pragma unroll
            for (int mt = 0; mt < 2; ++mt) {
                uint32_t addr = sA
                    + (uint32_t)(wm + mt * 16 + (lane & 15)) * 80u
                    + (uint32_t)(ks + ((lane >> 4) << 4));
                ldmx4(addr, af[mt][0], af[mt][1], af[mt][2], af[mt][3]);
            }
            uint32_t bf[8][2];
            #pragma unroll
            for (int nt2 = 0; nt2 < 4; ++nt2) {
                int n = wn + nt2 * 16 + (lane & 7) + ((lane >> 4) << 3);
                uint32_t addr = sBt + (uint32_t)n * 80u
                    + (uint32_t)(ks + (((lane >> 3) & 1) << 4));
                ldmx4(addr, bf[nt2*2][0], bf[nt2*2][1], bf[nt2*2+1][0], bf[nt2*2+1][1]);
            }
            #pragma unroll
            for (int mt = 0; mt < 2; ++mt)
                #pragma unroll
                for (int nt = 0; nt < 8; ++nt)
                    mma16832f8(acc[mt][nt], af[mt], bf[nt]);
        }
    }

    const float sa = amA ? scale_from(amA) : fixA;
    const float sw = scale_from(amW);
    const float inv = 1.f / (sa * sw);
    #pragma unroll
    for (int mt = 0; mt < 2; ++mt) {
        int row = m0 + wm + mt * 16 + (lane >> 2);
        #pragma unroll
        for (int nt = 0; nt < 8; ++nt) {
            int col = n0 + wn + nt * 8 + (lane & 3) * 2;
            if (col < N) {
                float b0 = bias ? bias[col]     : 0.f;
                float b1 = bias ? bias[col + 1] : 0.f;
                storev(C + (size_t)row * N + col,           acc[mt][nt][0] * inv + b0);
                storev(C + (size_t)row * N + col + 1,       acc[mt][nt][1] * inv + b1);
                storev(C + (size_t)(row + 8) * N + col,     acc[mt][nt][2] * inv + b0);
                storev(C + (size_t)(row + 8) * N + col + 1, acc[mt][nt][3] * inv + b1);
            }
        }
    }
}

// ---------------- amax / quant ----------------------------------------------
__global__ void zero_amax(unsigned* am) { if (threadIdx.x < 4) am[threadIdx.x] = 0u; }

// amax over f32 array, optionally scaled per-k by rms (rms != null)
__global__ void amax_f32(const float* __restrict__ w, const float* __restrict__ rms,
                         size_t n, int K, unsigned* __restrict__ am) {
    size_t i = (size_t)blockIdx.x * 1024 + threadIdx.x * 4;
    float m = 0.f;
    if (i + 3 < n) {
        float4 v = *(const float4*)(w + i);
        float r0 = rms ? rms[(i+0) % K] : 1.f, r1 = rms ? rms[(i+1) % K] : 1.f;
        float r2 = rms ? rms[(i+2) % K] : 1.f, r3 = rms ? rms[(i+3) % K] : 1.f;
        m = fmaxf(fmaxf(fabsf(v.x*r0), fabsf(v.y*r1)), fmaxf(fabsf(v.z*r2), fabsf(v.w*r3)));
    } else {
        for (size_t j = i; j < n; ++j) {
            float r = rms ? rms[j % K] : 1.f;
            m = fmaxf(m, fabsf(w[j]*r));
        }
    }
    #pragma unroll
    for (int o = 16; o > 0; o >>= 1) m = fmaxf(m, __shfl_xor_sync(0xffffffffu, m, o));
    if ((threadIdx.x & 31) == 0) atomicMax(am, __float_as_uint(m));
}
__global__ void amax_bf16(const __nv_bfloat16* __restrict__ w, size_t n, unsigned* __restrict__ am) {
    size_t i = (size_t)blockIdx.x * 2048 + threadIdx.x * 8;
    float m = 0.f;
    if (i + 7 < n) {
        uint4 v = *(const uint4*)(w + i);
        const __nv_bfloat16* p = (const __nv_bfloat16*)&v;
        #pragma unroll
        for (int j = 0; j < 8; ++j) m = fmaxf(m, fabsf(__bfloat162float(p[j])));
    } else {
        for (size_t j = i; j < n; ++j) m = fmaxf(m, fabsf(__bfloat162float(w[j])));
    }
    #pragma unroll
    for (int o = 16; o > 0; o >>= 1) m = fmaxf(m, __shfl_xor_sync(0xffffffffu, m, o));
    if ((threadIdx.x & 31) == 0) atomicMax(am, __float_as_uint(m));
}
// quantize f32 weights [N,K] -> fp8 [Npad,K], optional per-k rms fold
__global__ void quant_w8(const float* __restrict__ w, const float* __restrict__ rms,
                         uint8_t* __restrict__ o, int N, int K, int Npad,
                         const unsigned* __restrict__ am) {
    int idx = blockIdx.x * 256 + threadIdx.x;
    if (idx >= Npad * K) return;
    float s = scale_from(am);
    float v = 0.f;
    if (idx < N * K) {
        v = w[idx] * s;
        if (rms) v *= rms[idx % K];
    }
    o[idx] = to_fp8(v);
}
__global__ void quant_a8(const __nv_bfloat16* __restrict__ a, uint8_t* __restrict__ o,
                         size_t n, const unsigned* __restrict__ am) {
    size_t i = (size_t)blockIdx.x * 2048 + threadIdx.x * 8;
    if (i >= n) return;
    float s = scale_from(am);
    uint4 v = *(const uint4*)(a + i);
    const __nv_bfloat16* p = (const __nv_bfloat16*)&v;
    uint8_t q[8];
    #pragma unroll
    for (int j = 0; j < 8; ++j) q[j] = to_fp8(__bfloat162float(p[j]) * s);
    *(uint2*)(o + i) = *(uint2*)q;
}

// ---------------- weight products / folds ------------------------------------
__global__ void wmul_kernel(const float* __restrict__ A, const float* __restrict__ B,
                            __nv_bfloat16* __restrict__ C, int M, int N, int K)
{
    int lane = threadIdx.x & 31, w = threadIdx.x >> 5;
    int m = blockIdx.y * 8 + w;
    int n = blockIdx.x * 32 + lane;
    if (m >= M || n >= N) return;
    float s = 0.f;
    const float* ar = A + (size_t)m * K;
    const float* bc = B + n;
    for (int k = 0; k < K; ++k) s += ar[k] * bc[(size_t)k * N];
    C[(size_t)m * N + n] = __float2bfloat16(s);
}
__global__ void bfold_kernel(const float* __restrict__ W, const float* __restrict__ bin,
                             const float* __restrict__ badd, float* __restrict__ bout,
                             int N, int K) {
    int lane = threadIdx.x & 31, w = threadIdx.x >> 5;
    int n = blockIdx.x * 8 + w;
    if (n >= N) return;
    float s = 0.f;
    for (int k = lane; k < K; k += 32) s += W[(size_t)n * K + k] * bin[k];
    #pragma unroll
    for (int off = 16; off > 0; off >>= 1) s += __shfl_xor_sync(0xffffffffu, s, off);
    if (lane == 0) bout[n] = s + badd[n];
}

// ---------------- GroupNorm ---------------------------------------------------
__global__ void gn_stats(const float* __restrict__ x, float* __restrict__ st) {
    int n = blockIdx.x >> 5, g = blockIdx.x & 31;
    const int CPG = C_ / GROUPS;
    const float* base = x + ((size_t)n * C_ + g * CPG) * HW;
    float s = 0.f, ss = 0.f;
    for (int i = threadIdx.x; i < CPG * HW; i += 256) { float v = base[i]; s += v; ss += v * v; }
    __shared__ float rs[256], rq[256];
    rs[threadIdx.x] = s; rq[threadIdx.x] = ss; __syncthreads();
    for (int o = 128; o > 0; o >>= 1) {
        if (threadIdx.x < o) { rs[threadIdx.x] += rs[threadIdx.x + o]; rq[threadIdx.x] += rq[threadIdx.x + o]; }
        __syncthreads();
    }
    if (threadIdx.x == 0) {
        float mean = rs[0] / (CPG * HW);
        float var  = rq[0] / (CPG * HW) - mean * mean;
        st[blockIdx.x * 2]     = mean;
        st[blockIdx.x * 2 + 1] = rsqrtf(var + 1e-5f);
    }
}
__global__ void gn_apply(const float* __restrict__ x, const float* __restrict__ st,
                         const float* __restrict__ w, const float* __restrict__ b,
                         __nv_bfloat16* __restrict__ out) {
    __shared__ float tile[32][33];
    int c0 = blockIdx.x * 32, hw0 = blockIdx.y * 32, n = blockIdx.z;
    int tx = threadIdx.x & 31, ty = threadIdx.x >> 5;
    #pragma unroll
    for (int r = 0; r < 4; ++r) {
        int c = c0 + ty + r * 8;
        int g = c / 10;
        float mean = st[(n * 32 + g) * 2], inv = st[(n * 32 + g) * 2 + 1];
        float v = x[((size_t)n * C_ + c) * HW + hw0 + tx];
        tile[ty + r * 8][tx] = (v - mean) * inv * w[c] + b[c];
    }
    __syncthreads();
    #pragma unroll
    for (int r = 0; r < 4; ++r) {
        int hw = hw0 + ty + r * 8;
        out[((size_t)n * HW + hw) * C_ + c0 + tx] = __float2bfloat16(tile[tx][ty + r * 8]);
    }
}

// ---------------- fused dt + conv + SSM + gate + RMSNorm ---------------------
// emits fp8 y (unit-RMS; rms_w folded into out_proj weights) at scale YSCALE.
#define CDP 1282
#define MAMBA_SMEM 167104
__global__ void __launch_bounds__(512)
mamba_fused(const __nv_bfloat16* __restrict__ zx, const float* __restrict__ cw,
            const float* __restrict__ cb, const float* __restrict__ dt_bias,
            const float* __restrict__ A_log, const float* __restrict__ Dv,
            uint8_t* __restrict__ yb)
{
    extern __shared__ char sm[];
    float* sx     = (float*)sm;
    float* sy     = (float*)(sm + 82048);
    float* sW     = (float*)(sm + 147584);
    float* sScore = (float*)(sm + 163968);
    float* sDt    = (float*)(sm + 164992);
    float* sCum   = (float*)(sm + 166016);
    float* sSq    = (float*)(sm + 167040);
    const int s = blockIdx.x, tid = threadIdx.x;
    const __nv_bfloat16* zb = zx + (size_t)s * L_ * D_IN_PROJ;

    if (tid < 256) {
        int l = tid >> 4, h = tid & 15;
        float v = __bfloat162float(zb[(size_t)l * D_IN_PROJ + D_INNER + CONV_DIM + h]) + dt_bias[h];
        sDt[l * 16 + h] = (v > 20.f) ? v : log1pf(expf(v));
    }
    if (tid < 16) sSq[tid] = 0.f;

    for (int c = tid; c < CONV_DIM; c += 512) {
        float w0 = cw[c*4], w1 = cw[c*4+1], w2 = cw[c*4+2], w3 = cw[c*4+3];
        float bb = cb[c];
        float v0 = 0.f, v1 = 0.f, v2 = 0.f;
        const __nv_bfloat16* base = zb + D_INNER + c;
        #pragma unroll
        for (int l = 0; l < L_; ++l) {
            float v3 = __bfloat162float(base[(size_t)l * D_IN_PROJ]);
            float o = v0*w0 + v1*w1 + v2*w2 + v3*w3 + bb;
            o = o / (1.f + expf(-o));
            sx[l * CDP + c] = o;
            v0 = v1; v1 = v2; v2 = v3;
        }
    }
    __syncthreads();

    if (tid < 256) {
        int l = tid >> 4, sp = tid & 15;
        float acc = 0.f;
        #pragma unroll 8
        for (int n = 0; n < D_STATE; ++n)
            acc += sx[l * CDP + D_INNER + D_STATE + n] * sx[sp * CDP + D_INNER + n];
        sScore[l * 16 + sp] = acc;
    } else if (tid < 272) {
        int h = tid - 256;
        float a = -expf(A_log[h]);
        float run = 0.f;
        #pragma unroll
        for (int l = 0; l < L_; ++l) { run += sDt[l * 16 + h] * a; sCum[l * 16 + h] = run; }
    }
    __syncthreads();

    for (int i = tid; i < NHEADS * 256; i += 512) {
        int h = i >> 8, l = (i >> 4) & 15, sp = i & 15;
        float w;
        if (sp < l)       w = sScore[l*16+sp] * expf(sCum[l*16+h] - sCum[sp*16+h]) * sDt[sp*16+h];
        else if (sp == l) w = sScore[l*16+l] * sDt[l*16+h] + Dv[h];
        else              w = 0.f;
        sW[(h * 16 + l) * 16 + sp] = w;
    }
    __syncthreads();

    const int h = tid >> 5, lane = tid & 31;
    float x0[L_], x1[L_];
    #pragma unroll
    for (int sp = 0; sp < L_; ++sp) {
        x0[sp] = sx[sp * CDP + h * HEADDIM + lane];
        x1[sp] = sx[sp * CDP + h * HEADDIM + lane + 32];
    }
    #pragma unroll
    for (int l = 0; l < L_; ++l) {
        float a0 = 0.f, a1 = 0.f;
        for (int sp = 0; sp <= l; ++sp) {
            float w = sW[(h * 16 + l) * 16 + sp];
            a0 += w * x0[sp]; a1 += w * x1[sp];
        }
        float z0 = __bfloat162float(zb[(size_t)l * D_IN_PROJ + h * HEADDIM + lane]);
        float z1 = __bfloat162float(zb[(size_t)l * D_IN_PROJ + h * HEADDIM + lane + 32]);
        a0 *= z0 / (1.f + expf(-z0));
        a1 *= z1 / (1.f + expf(-z1));
        sy[l * 1024 + h * HEADDIM + lane]      = a0;
        sy[l * 1024 + h * HEADDIM + lane + 32] = a1;
        float q = a0 * a0 + a1 * a1;
        #pragma unroll
        for (int off = 16; off > 0; off >>= 1) q += __shfl_xor_sync(0xffffffffu, q, off);
        if (lane == 0) atomicAdd(&sSq[l], q);
    }
    __syncthreads();
    if (tid < 16) sSq[tid] = rsqrtf(sSq[tid] / (float)D_INNER + 1e-5f) * YSCALE;
    __syncthreads();

    uint8_t* ob = yb + (size_t)s * L_ * D_INNER;
    for (int i = tid; i < L_ * D_INNER; i += 512) {
        int l = i >> 10, d = i & 1023;
        ob[i] = to_fp8(sy[l * 1024 + d] * sSq[l]);
    }
}

// ---------------- final: residual + transpose --------------------------------
__global__ void final_t(const float* __restrict__ x, const float* __restrict__ c2,
                        const float* __restrict__ gamma, float* __restrict__ out) {
    __shared__ float tile[32][33];
    int c0 = blockIdx.x * 32, hw0 = blockIdx.y * 32, n = blockIdx.z;
    int tx = threadIdx.x & 31, ty = threadIdx.x >> 5;
    #pragma unroll
    for (int r = 0; r < 4; ++r) {
        int hw = hw0 + ty + r * 8;
        tile[ty + r * 8][tx] = c2[((size_t)n * HW + hw) * C_ + c0 + tx];
    }
    __syncthreads();
    float gm = gamma[0];
    #pragma unroll
    for (int r = 0; r < 4; ++r) {
        int c = c0 + ty + r * 8;
        size_t idx = ((size_t)n * C_ + c) * HW + hw0 + tx;
        out[idx] = x[idx] + gm * tile[tx][ty + r * 8];
    }
}

// ---------------- launch -------------------------------------------------------
extern "C" void kernel_launch(void* const* d_in, const int* in_sizes, int n_in,
                              void* d_out, int out_size) {
    const float* x          = (const float*)d_in[0];
    const float* norm_w     = (const float*)d_in[1];
    const float* norm_b     = (const float*)d_in[2];
    const float* proj_in_w  = (const float*)d_in[3];
    const float* proj_in_b  = (const float*)d_in[4];
    const float* expand_w   = (const float*)d_in[5];
    const float* expand_b   = (const float*)d_in[6];
    const float* in_proj_w  = (const float*)d_in[7];
    const float* conv_w     = (const float*)d_in[8];
    const float* conv_b     = (const float*)d_in[9];
    const float* dt_bias    = (const float*)d_in[10];
    const float* A_log      = (const float*)d_in[11];
    const float* Dv         = (const float*)d_in[12];
    const float* rms_w      = (const float*)d_in[13];
    const float* out_proj_w = (const float*)d_in[14];
    const float* collapse_w = (const float*)d_in[15];
    const float* collapse_b = (const float*)d_in[16];
    const float* proj_out_w = (const float*)d_in[17];
    const float* proj_out_b = (const float*)d_in[18];
    const float* gamma      = (const float*)d_in[19];

    __nv_bfloat16 *a0, *a2, *zxb, *o1, *w21, *wf;
    uint8_t *a28, *yb8, *wi8, *wo8;
    float *c2, *gst, *b21, *bfin;
    unsigned *am;
    cudaGetSymbolAddress((void**)&a0,  g_a0);  cudaGetSymbolAddress((void**)&a2,  g_a2);
    cudaGetSymbolAddress((void**)&a28, g_a28); cudaGetSymbolAddress((void**)&zxb, g_zxb);
    cudaGetSymbolAddress((void**)&yb8, g_yb8); cudaGetSymbolAddress((void**)&o1,  g_o1);
    cudaGetSymbolAddress((void**)&c2,  g_c2);  cudaGetSymbolAddress((void**)&gst, g_gst);
    cudaGetSymbolAddress((void**)&w21, g_w21); cudaGetSymbolAddress((void**)&wf,  g_wf);
    cudaGetSymbolAddress((void**)&b21, g_b21); cudaGetSymbolAddress((void**)&bfin, g_bf);
    cudaGetSymbolAddress((void**)&wi8, g_wi8); cudaGetSymbolAddress((void**)&wo8, g_wo8);
    cudaGetSymbolAddress((void**)&am,  g_amax);

    cudaFuncSetAttribute((const void*)tc_gemm<__nv_bfloat16,0>, cudaFuncAttributeMaxDynamicSharedMemorySize, GEMM_SMEM);
    cudaFuncSetAttribute((const void*)tc_gemm<float,2>,         cudaFuncAttributeMaxDynamicSharedMemorySize, GEMM_SMEM);
    cudaFuncSetAttribute((const void*)tc_gemm8<__nv_bfloat16,1>, cudaFuncAttributeMaxDynamicSharedMemorySize, GEMM8_SMEM);
    cudaFuncSetAttribute((const void*)tc_gemm8<__nv_bfloat16,0>, cudaFuncAttributeMaxDynamicSharedMemorySize, GEMM8_SMEM);
    cudaFuncSetAttribute((const void*)mamba_fused,               cudaFuncAttributeMaxDynamicSharedMemorySize, MAMBA_SMEM);

    zero_amax<<<1, 32>>>(am);

    // 0a. fused weight products (bf16)
    { dim3 g((C_+31)/32, (CEXP+7)/8);
      wmul_kernel<<<g, 256>>>(expand_w, proj_in_w, w21, CEXP, C_, C_); }
    { dim3 g((CEXP+31)/32, (C_+7)/8);
      wmul_kernel<<<g, 256>>>(proj_out_w, collapse_w, wf, C_, CEXP, C_); }
    bfold_kernel<<<CEXP/8, 256>>>(expand_w,   proj_in_b,  expand_b,   b21,  CEXP, C_);
    bfold_kernel<<<C_/8,   256>>>(proj_out_w, collapse_b, proj_out_b, bfin, C_,   C_);

    // 0b. fp8 weight quantization (dynamic amax; rms folded into out_proj)
    { size_t n = (size_t)D_IN_PROJ * CEXP;
      amax_f32<<<(int)((n + 1023)/1024), 256>>>(in_proj_w, nullptr, n, CEXP, am + 0); }
    { size_t n = (size_t)CEXP * D_INNER;
      amax_f32<<<(int)((n + 1023)/1024), 256>>>(out_proj_w, rms_w, n, D_INNER, am + 1); }
    quant_w8<<<(NP2320*CEXP + 255)/256, 256>>>(in_proj_w, nullptr, wi8, D_IN_PROJ, CEXP, NP2320, am + 0);
    quant_w8<<<(CEXP*D_INNER + 255)/256, 256>>>(out_proj_w, rms_w, wo8, CEXP, D_INNER, CEXP, am + 1);

    // 1. GroupNorm
    gn_stats<<<NFRM*GROUPS, 256>>>(x, gst);
    { dim3 g(C_/32, HW/32, NFRM); gn_apply<<<g, 256>>>(x, gst, norm_w, norm_b, a0); }

    // 2. fused proj_in+expand (bf16 HMMA)
    { dim3 g(CEXP/128, NTOK/128);
      tc_gemm<__nv_bfloat16,0><<<g, 256, GEMM_SMEM>>>(a0, w21, b21, a2, NTOK, CEXP, C_); }

    // 3. quantize a2 -> fp8 (dynamic)
    { size_t n = (size_t)NTOK * CEXP;
      amax_bf16<<<(int)((n + 2047)/2048), 256>>>(a2, n, am + 2);
      quant_a8<<<(int)((n + 2047)/2048), 256>>>(a2, a28, n, am + 2); }

    // 4. in_proj (fp8 QMMA, fused fwd permute)
    { dim3 g(NP2320/128, NTOK/128);
      tc_gemm8<__nv_bfloat16,1><<<g, 256, GEMM8_SMEM>>>(a28, wi8, am + 2, 0.f, am + 0,
                                                        nullptr, zxb, NTOK, D_IN_PROJ, CEXP); }
    // 5. fused dt+conv+SSM+gate+RMSNorm -> fp8 y (scale YSCALE)
    mamba_fused<<<NSEQ, 512, MAMBA_SMEM>>>(zxb, conv_w, conv_b, dt_bias, A_log, Dv, yb8);

    // 6. out_proj (fp8 QMMA; rms_w folded into weights)
    { dim3 g(CEXP/128, NTOK/128);
      tc_gemm8<__nv_bfloat16,0><<<g, 256, GEMM8_SMEM>>>(yb8, wo8, nullptr, YSCALE, am + 1,
                                                        nullptr, o1, NTOK, CEXP, D_INNER); }
    // 7. fused collapse+proj_out (bf16, bwd permute, fp32 out)
    { dim3 g(NPF/128, NTOK/128);
      tc_gemm<float,2><<<g, 256, GEMM_SMEM>>>(o1, wf, bfin, c2, NTOK, C_, CEXP); }
    // 8. residual + transpose
    { dim3 g(C_/32, HW/32, NFRM); final_t<<<g, 256>>>(x, c2, gamma, (float*)d_out); }
}

// round 8
// speedup vs baseline: 1.0689x; 1.0689x over previous
#include <cuda_runtime.h>
#include <cuda_bf16.h>
#include <math.h>
#include <cstdint>

#define B_      2
#define F_      16
#define H_      32
#define W_      32
#define HW      1024
#define NFRM    32
#define C_      320
#define CEXP    512
#define D_INNER 1024
#define NHEADS  16
#define HEADDIM 64
#define D_STATE 128
#define D_CONV  4
#define CONV_DIM 1280
#define D_IN_PROJ 2320
#define GROUPS  32
#define NSEQ    2048
#define L_      16
#define NTOK    32768

#define NP2320  2432
#define NPF     384

// ---------------- scratch ---------------------------------------------------
__device__ __nv_bfloat16 g_a0[(size_t)NTOK*C_];
__device__ __nv_bfloat16 g_zxb[(size_t)NTOK*D_IN_PROJ];
__device__ __nv_bfloat16 g_yb[(size_t)NTOK*D_INNER];
__device__ float         g_c2[(size_t)NTOK*C_];
__device__ float         g_gst[NFRM*GROUPS*2];
__device__ __nv_bfloat16 g_w21t[NPF*CEXP];             // (expand∘proj_in)^T  [384pad,512]
__device__ __nv_bfloat16 g_wibf[(size_t)NP2320*CEXP];  // in_proj bf16 [2432,512]
__device__ __nv_bfloat16 g_wiall[(size_t)NP2320*C_];   // fused front weight [2432,320]
__device__ __nv_bfloat16 g_wf1[NPF*CEXP];              // proj_out∘collapse [384pad,512]
__device__ __nv_bfloat16 g_opt[(size_t)D_INNER*CEXP];  // out_proj^T·rms [1024,512]
__device__ __nv_bfloat16 g_wfall[(size_t)NPF*D_INNER]; // fused back weight [384,1024]
__device__ float         g_b21[CEXP];
__device__ float         g_bi[D_IN_PROJ];
__device__ float         g_bf[C_];

// ---------------- PTX helpers ----------------------------------------------
__device__ __forceinline__ uint32_t smem_u32(const void* p) {
    uint32_t a;
    asm("{ .reg .u64 t; cvta.to.shared.u64 t, %1; cvt.u32.u64 %0, t; }" : "=r"(a) : "l"(p));
    return a;
}
__device__ __forceinline__ void cp16(uint32_t dst, const void* src) {
    asm volatile("cp.async.cg.shared.global [%0], [%1], 16;" :: "r"(dst), "l"(src) : "memory");
}
__device__ __forceinline__ void ldmx4(uint32_t addr, uint32_t& r0, uint32_t& r1,
                                      uint32_t& r2, uint32_t& r3) {
    asm volatile("ldmatrix.sync.aligned.m8n8.x4.shared.b16 {%0,%1,%2,%3}, [%4];"
                 : "=r"(r0), "=r"(r1), "=r"(r2), "=r"(r3) : "r"(addr));
}
__device__ __forceinline__ void mma16816(float* c, const uint32_t* a, const uint32_t* b) {
    asm volatile("mma.sync.aligned.m16n8k16.row.col.f32.bf16.bf16.f32 "
                 "{%0,%1,%2,%3}, {%4,%5,%6,%7}, {%8,%9}, {%0,%1,%2,%3};"
                 : "+f"(c[0]), "+f"(c[1]), "+f"(c[2]), "+f"(c[3])
                 : "r"(a[0]), "r"(a[1]), "r"(a[2]), "r"(a[3]), "r"(b[0]), "r"(b[1]));
}
__device__ __forceinline__ void storev(float* p, float v)         { *p = v; }
__device__ __forceinline__ void storev(__nv_bfloat16* p, float v) { *p = __float2bfloat16(v); }

// row remap for fused permutes
template<int PERM> __device__ __forceinline__ int rowmap(int r) {
    if (PERM == 1) {            // dest seq-order, src frame-order
        int f = r & 15, hw = (r >> 4) & 1023, bb = r >> 14;
        return bb * 16384 + f * 1024 + hw;
    } else if (PERM == 2) {     // dest frame-order, src seq-order
        int hw = r & 1023, f = (r >> 10) & 15, bb = r >> 14;
        return bb * 16384 + hw * 16 + f;
    }
    return r;
}

// ---------------- bf16 HMMA GEMM (128x128x64, 3-stage) -----------------------
// C[M,N] = A[perm(M),K] @ B[N,K]^T (+bias[n]); M%128==0, K%64==0, N even.
#define GEMM_SMEM (3*2*18432)   // 110592
template<typename OutT, int PERM>
__global__ void __launch_bounds__(256, 2)
tc_gemm(const __nv_bfloat16* __restrict__ A, const __nv_bfloat16* __restrict__ B,
        const float* __restrict__ bias, OutT* __restrict__ C, int M, int N, int K)
{
    extern __shared__ char smraw[];
    const uint32_t sbase = smem_u32(smraw);
    const int tid = threadIdx.x;
    const int lane = tid & 31, warp = tid >> 5;
    const int wm = (warp & 3) * 32, wn = (warp >> 2) * 64;
    const int m0 = blockIdx.y * 128, n0 = blockIdx.x * 128;

    const int seg = tid & 7, r0 = tid >> 3;
    int arows[4];
    #pragma unroll
    for (int j = 0; j < 4; ++j) arows[j] = rowmap<PERM>(m0 + r0 + j * 32);

    float acc[2][8][4];
    #pragma unroll
    for (int i = 0; i < 2; ++i)
        #pragma unroll
        for (int j = 0; j < 8; ++j)
            #pragma unroll
            for (int k = 0; k < 4; ++k) acc[i][j][k] = 0.f;

    const int nc = K >> 6;
    auto load = [&](int i) {
        const uint32_t da = sbase + (uint32_t)(i % 3) * 36864u;
        const uint32_t db = da + 18432u;
        const int k0 = i << 6;
        #pragma unroll
        for (int j = 0; j < 4; ++j) {
            int row = r0 + j * 32;
            uint32_t off = (uint32_t)row * 144u + (uint32_t)seg * 16u;
            cp16(da + off, A + (size_t)arows[j] * K + k0 + seg * 8);
            cp16(db + off, B + (size_t)(n0 + row) * K + k0 + seg * 8);
        }
        asm volatile("cp.async.commit_group;" ::: "memory");
    };

    load(0);
    if (nc > 1) load(1);

    for (int i = 0; i < nc; ++i) {
        if (i + 1 < nc) asm volatile("cp.async.wait_group 1;" ::: "memory");
        else            asm volatile("cp.async.wait_group 0;" ::: "memory");
        __syncthreads();
        if (i + 2 < nc) load(i + 2);

        const uint32_t sA  = sbase + (uint32_t)(i % 3) * 36864u;
        const uint32_t sBt = sA + 18432u;
        #pragma unroll
        for (int ks = 0; ks < 64; ks += 16) {
            uint32_t af[2][4];
            #pragma unroll
            for (int mt = 0; mt < 2; ++mt) {
                uint32_t addr = sA
                    + (uint32_t)(wm + mt * 16 + (lane & 15)) * 144u
                    + (uint32_t)(ks + ((lane >> 4) << 3)) * 2u;
                ldmx4(addr, af[mt][0], af[mt][1], af[mt][2], af[mt][3]);
            }
            uint32_t bf[8][2];
            #pragma unroll
            for (int nt2 = 0; nt2 < 4; ++nt2) {
                int n  = wn + nt2 * 16 + (lane & 7) + ((lane >> 4) << 3);
                int kk = ks + (((lane >> 3) & 1) << 3);
                uint32_t addr = sBt + (uint32_t)n * 144u + (uint32_t)kk * 2u;
                ldmx4(addr, bf[nt2*2][0], bf[nt2*2][1], bf[nt2*2+1][0], bf[nt2*2+1][1]);
            }
            #pragma unroll
            for (int mt = 0; mt < 2; ++mt)
                #pragma unroll
                for (int nt = 0; nt < 8; ++nt)
                    mma16816(acc[mt][nt], af[mt], bf[nt]);
        }
    }

    #pragma unroll
    for (int mt = 0; mt < 2; ++mt) {
        int row = m0 + wm + mt * 16 + (lane >> 2);
        #pragma unroll
        for (int nt = 0; nt < 8; ++nt) {
            int col = n0 + wn + nt * 8 + (lane & 3) * 2;
            if (col < N) {
                float b0 = bias ? bias[col]     : 0.f;
                float b1 = bias ? bias[col + 1] : 0.f;
                storev(C + (size_t)row * N + col,           acc[mt][nt][0] + b0);
                storev(C + (size_t)row * N + col + 1,       acc[mt][nt][1] + b1);
                storev(C + (size_t)(row + 8) * N + col,     acc[mt][nt][2] + b0);
                storev(C + (size_t)(row + 8) * N + col + 1, acc[mt][nt][3] + b1);
            }
        }
    }
}

// ---------------- weight-prep kernels ----------------------------------------
// C[m,n] = sum_k A[m,k]*B[k,n] -> bf16 [Mpad,N] (zero rows m>=M)
__global__ void wmul_kernel(const float* __restrict__ A, const float* __restrict__ B,
                            __nv_bfloat16* __restrict__ C, int M, int N, int K, int Mpad)
{
    int lane = threadIdx.x & 31, w = threadIdx.x >> 5;
    int m = blockIdx.y * 8 + w;
    int n = blockIdx.x * 32 + lane;
    if (m >= Mpad || n >= N) return;
    float s = 0.f;
    if (m < M) {
        const float* ar = A + (size_t)m * K;
        const float* bc = B + n;
        for (int k = 0; k < K; ++k) s += ar[k] * bc[(size_t)k * N];
    }
    C[(size_t)m * N + n] = __float2bfloat16(s);
}
// C[r,m] = sum_k A[m,k]*B[k,r] -> bf16 [Rpad,M] ((A@B)^T, zero rows r>=R)
__global__ void wmul_t_kernel(const float* __restrict__ A, const float* __restrict__ B,
                              __nv_bfloat16* __restrict__ C, int M, int R, int K, int Rpad)
{
    int lane = threadIdx.x & 31, w = threadIdx.x >> 5;
    int r = blockIdx.y * 8 + w;
    int m = blockIdx.x * 32 + lane;
    if (r >= Rpad || m >= M) return;
    float s = 0.f;
    if (r < R) {
        const float* ar = A + (size_t)m * K;
        const float* bc = B + r;
        for (int k = 0; k < K; ++k) s += ar[k] * bc[(size_t)k * R];
    }
    C[(size_t)r * M + m] = __float2bfloat16(s);
}
// bias fold: bout[n] = dot(W[n,:], bin) (+ badd[n] if badd)
__global__ void bfold_kernel(const float* __restrict__ W, const float* __restrict__ bin,
                             const float* __restrict__ badd, float* __restrict__ bout,
                             int N, int K) {
    int lane = threadIdx.x & 31, w = threadIdx.x >> 5;
    int n = blockIdx.x * 8 + w;
    if (n >= N) return;
    float s = 0.f;
    for (int k = lane; k < K; k += 32) s += W[(size_t)n * K + k] * bin[k];
    #pragma unroll
    for (int off = 16; off > 0; off >>= 1) s += __shfl_xor_sync(0xffffffffu, s, off);
    if (lane == 0) bout[n] = s + (badd ? badd[n] : 0.f);
}
// fp32 [N,K] -> bf16 [Npad,K] (zero pad)
__global__ void wconv_kernel(const float* __restrict__ w, __nv_bfloat16* __restrict__ o,
                             int N, int K, int Npad) {
    int idx = blockIdx.x * 256 + threadIdx.x;
    if (idx >= Npad * K) return;
    o[idx] = __float2bfloat16(idx < N * K ? w[idx] : 0.f);
}
// opT[d,o] = out_proj[o,d] * rms[d]  ([512,1024] fp32 -> [1024,512] bf16)
__global__ void op_t_kernel(const float* __restrict__ W, const float* __restrict__ rms,
                            __nv_bfloat16* __restrict__ o) {
    __shared__ float t[32][33];
    int o0 = blockIdx.x * 32, d0 = blockIdx.y * 32;
    int tx = threadIdx.x & 31, ty = threadIdx.x >> 5;
    #pragma unroll
    for (int r = 0; r < 4; ++r)
        t[ty + r * 8][tx] = W[(size_t)(o0 + ty + r * 8) * D_INNER + d0 + tx];
    __syncthreads();
    #pragma unroll
    for (int r = 0; r < 4; ++r) {
        int d = d0 + ty + r * 8;
        o[(size_t)d * CEXP + o0 + tx] = __float2bfloat16(t[tx][ty + r * 8] * rms[d]);
    }
}

// ---------------- GroupNorm ---------------------------------------------------
__global__ void gn_stats(const float* __restrict__ x, float* __restrict__ st) {
    int n = blockIdx.x >> 5, g = blockIdx.x & 31;
    const int CPG = C_ / GROUPS;
    const float* base = x + ((size_t)n * C_ + g * CPG) * HW;
    float s = 0.f, ss = 0.f;
    for (int i = threadIdx.x; i < CPG * HW; i += 256) { float v = base[i]; s += v; ss += v * v; }
    __shared__ float rs[256], rq[256];
    rs[threadIdx.x] = s; rq[threadIdx.x] = ss; __syncthreads();
    for (int o = 128; o > 0; o >>= 1) {
        if (threadIdx.x < o) { rs[threadIdx.x] += rs[threadIdx.x + o]; rq[threadIdx.x] += rq[threadIdx.x + o]; }
        __syncthreads();
    }
    if (threadIdx.x == 0) {
        float mean = rs[0] / (CPG * HW);
        float var  = rq[0] / (CPG * HW) - mean * mean;
        st[blockIdx.x * 2]     = mean;
        st[blockIdx.x * 2 + 1] = rsqrtf(var + 1e-5f);
    }
}
__global__ void gn_apply(const float* __restrict__ x, const float* __restrict__ st,
                         const float* __restrict__ w, const float* __restrict__ b,
                         __nv_bfloat16* __restrict__ out) {
    __shared__ float tile[32][33];
    int c0 = blockIdx.x * 32, hw0 = blockIdx.y * 32, n = blockIdx.z;
    int tx = threadIdx.x & 31, ty = threadIdx.x >> 5;
    #pragma unroll
    for (int r = 0; r < 4; ++r) {
        int c = c0 + ty + r * 8;
        int g = c / 10;
        float mean = st[(n * 32 + g) * 2], inv = st[(n * 32 + g) * 2 + 1];
        float v = x[((size_t)n * C_ + c) * HW + hw0 + tx];
        tile[ty + r * 8][tx] = (v - mean) * inv * w[c] + b[c];
    }
    __syncthreads();
    #pragma unroll
    for (int r = 0; r < 4; ++r) {
        int hw = hw0 + ty + r * 8;
        out[((size_t)n * HW + hw) * C_ + c0 + tx] = __float2bfloat16(tile[tx][ty + r * 8]);
    }
}

// ---------------- fused dt + conv + SSM + gate + RMSNorm ---------------------
// emits unit-RMS bf16 y (rms_w folded into back weights)
#define CDP 1282
#define MAMBA_SMEM 167104
__global__ void __launch_bounds__(512)
mamba_fused(const __nv_bfloat16* __restrict__ zx, const float* __restrict__ cw,
            const float* __restrict__ cb, const float* __restrict__ dt_bias,
            const float* __restrict__ A_log, const float* __restrict__ Dv,
            __nv_bfloat16* __restrict__ yb)
{
    extern __shared__ char sm[];
    float* sx     = (float*)sm;
    float* sy     = (float*)(sm + 82048);
    float* sW     = (float*)(sm + 147584);
    float* sScore = (float*)(sm + 163968);
    float* sDt    = (float*)(sm + 164992);
    float* sCum   = (float*)(sm + 166016);
    float* sSq    = (float*)(sm + 167040);
    const int s = blockIdx.x, tid = threadIdx.x;
    const __nv_bfloat16* zb = zx + (size_t)s * L_ * D_IN_PROJ;

    if (tid < 256) {
        int l = tid >> 4, h = tid & 15;
        float v = __bfloat162float(zb[(size_t)l * D_IN_PROJ + D_INNER + CONV_DIM + h]) + dt_bias[h];
        sDt[l * 16 + h] = (v > 20.f) ? v : log1pf(expf(v));
    }
    if (tid < 16) sSq[tid] = 0.f;

    for (int c = tid; c < CONV_DIM; c += 512) {
        float w0 = cw[c*4], w1 = cw[c*4+1], w2 = cw[c*4+2], w3 = cw[c*4+3];
        float bb = cb[c];
        float v0 = 0.f, v1 = 0.f, v2 = 0.f;
        const __nv_bfloat16* base = zb + D_INNER + c;
        #pragma unroll
        for (int l = 0; l < L_; ++l) {
            float v3 = __bfloat162float(base[(size_t)l * D_IN_PROJ]);
            float o = v0*w0 + v1*w1 + v2*w2 + v3*w3 + bb;
            o = o / (1.f + expf(-o));
            sx[l * CDP + c] = o;
            v0 = v1; v1 = v2; v2 = v3;
        }
    }
    __syncthreads();

    if (tid < 256) {
        int l = tid >> 4, sp = tid & 15;
        float acc = 0.f;
        #pragma unroll 8
        for (int n = 0; n < D_STATE; ++n)
            acc += sx[l * CDP + D_INNER + D_STATE + n] * sx[sp * CDP + D_INNER + n];
        sScore[l * 16 + sp] = acc;
    } else if (tid < 272) {
        int h = tid - 256;
        float a = -expf(A_log[h]);
        float run = 0.f;
        #pragma unroll
        for (int l = 0; l < L_; ++l) { run += sDt[l * 16 + h] * a; sCum[l * 16 + h] = run; }
    }
    __syncthreads();

    for (int i = tid; i < NHEADS * 256; i += 512) {
        int h = i >> 8, l = (i >> 4) & 15, sp = i & 15;
        float w;
        if (sp < l)       w = sScore[l*16+sp] * expf(sCum[l*16+h] - sCum[sp*16+h]) * sDt[sp*16+h];
        else if (sp == l) w = sScore[l*16+l] * sDt[l*16+h] + Dv[h];
        else              w = 0.f;
        sW[(h * 16 + l) * 16 + sp] = w;
    }
    __syncthreads();

    const int h = tid >> 5, lane = tid & 31;
    float x0[L_], x1[L_];
    #pragma unroll
    for (int sp = 0; sp < L_; ++sp) {
        x0[sp] = sx[sp * CDP + h * HEADDIM + lane];
        x1[sp] = sx[sp * CDP + h * HEADDIM + lane + 32];
    }
    #pragma unroll
    for (int l = 0; l < L_; ++l) {
        float a0 = 0.f, a1 = 0.f;
        for (int sp = 0; sp <= l; ++sp) {
            float w = sW[(h * 16 + l) * 16 + sp];
            a0 += w * x0[sp]; a1 += w * x1[sp];
        }
        float z0 = __bfloat162float(zb[(size_t)l * D_IN_PROJ + h * HEADDIM + lane]);
        float z1 = __bfloat162float(zb[(size_t)l * D_IN_PROJ + h * HEADDIM + lane + 32]);
        a0 *= z0 / (1.f + expf(-z0));
        a1 *= z1 / (1.f + expf(-z1));
        sy[l * 1024 + h * HEADDIM + lane]      = a0;
        sy[l * 1024 + h * HEADDIM + lane + 32] = a1;
        float q = a0 * a0 + a1 * a1;
        #pragma unroll
        for (int off = 16; off > 0; off >>= 1) q += __shfl_xor_sync(0xffffffffu, q, off);
        if (lane == 0) atomicAdd(&sSq[l], q);
    }
    __syncthreads();
    if (tid < 16) sSq[tid] = rsqrtf(sSq[tid] / (float)D_INNER + 1e-5f);
    __syncthreads();

    __nv_bfloat16* ob = yb + (size_t)s * L_ * D_INNER;
    for (int i = tid; i < L_ * D_INNER; i += 512) {
        int l = i >> 10, d = i & 1023;
        ob[i] = __float2bfloat16(sy[l * 1024 + d] * sSq[l]);
    }
}

// ---------------- final: residual + transpose --------------------------------
__global__ void final_t(const float* __restrict__ x, const float* __restrict__ c2,
                        const float* __restrict__ gamma, float* __restrict__ out) {
    __shared__ float tile[32][33];
    int c0 = blockIdx.x * 32, hw0 = blockIdx.y * 32, n = blockIdx.z;
    int tx = threadIdx.x & 31, ty = threadIdx.x >> 5;
    #pragma unroll
    for (int r = 0; r < 4; ++r) {
        int hw = hw0 + ty + r * 8;
        tile[ty + r * 8][tx] = c2[((size_t)n * HW + hw) * C_ + c0 + tx];
    }
    __syncthreads();
    float gm = gamma[0];
    #pragma unroll
    for (int r = 0; r < 4; ++r) {
        int c = c0 + ty + r * 8;
        size_t idx = ((size_t)n * C_ + c) * HW + hw0 + tx;
        out[idx] = x[idx] + gm * tile[tx][ty + r * 8];
    }
}

// ---------------- launch -------------------------------------------------------
extern "C" void kernel_launch(void* const* d_in, const int* in_sizes, int n_in,
                              void* d_out, int out_size) {
    const float* x          = (const float*)d_in[0];
    const float* norm_w     = (const float*)d_in[1];
    const float* norm_b     = (const float*)d_in[2];
    const float* proj_in_w  = (const float*)d_in[3];
    const float* proj_in_b  = (const float*)d_in[4];
    const float* expand_w   = (const float*)d_in[5];
    const float* expand_b   = (const float*)d_in[6];
    const float* in_proj_w  = (const float*)d_in[7];
    const float* conv_w     = (const float*)d_in[8];
    const float* conv_b     = (const float*)d_in[9];
    const float* dt_bias    = (const float*)d_in[10];
    const float* A_log      = (const float*)d_in[11];
    const float* Dv         = (const float*)d_in[12];
    const float* rms_w      = (const float*)d_in[13];
    const float* out_proj_w = (const float*)d_in[14];
    const float* collapse_w = (const float*)d_in[15];
    const float* collapse_b = (const float*)d_in[16];
    const float* proj_out_w = (const float*)d_in[17];
    const float* proj_out_b = (const float*)d_in[18];
    const float* gamma      = (const float*)d_in[19];

    __nv_bfloat16 *a0, *zxb, *yb, *w21t, *wibf, *wiall, *wf1, *opt, *wfall;
    float *c2, *gst, *b21, *bi, *bfin;
    cudaGetSymbolAddress((void**)&a0,   g_a0);   cudaGetSymbolAddress((void**)&zxb,  g_zxb);
    cudaGetSymbolAddress((void**)&yb,   g_yb);   cudaGetSymbolAddress((void**)&c2,   g_c2);
    cudaGetSymbolAddress((void**)&gst,  g_gst);
    cudaGetSymbolAddress((void**)&w21t, g_w21t); cudaGetSymbolAddress((void**)&wibf, g_wibf);
    cudaGetSymbolAddress((void**)&wiall,g_wiall);cudaGetSymbolAddress((void**)&wf1,  g_wf1);
    cudaGetSymbolAddress((void**)&opt,  g_opt);  cudaGetSymbolAddress((void**)&wfall,g_wfall);
    cudaGetSymbolAddress((void**)&b21,  g_b21);  cudaGetSymbolAddress((void**)&bi,   g_bi);
    cudaGetSymbolAddress((void**)&bfin, g_bf);

    cudaFuncSetAttribute((const void*)tc_gemm<__nv_bfloat16,0>, cudaFuncAttributeMaxDynamicSharedMemorySize, GEMM_SMEM);
    cudaFuncSetAttribute((const void*)tc_gemm<__nv_bfloat16,1>, cudaFuncAttributeMaxDynamicSharedMemorySize, GEMM_SMEM);
    cudaFuncSetAttribute((const void*)tc_gemm<float,2>,         cudaFuncAttributeMaxDynamicSharedMemorySize, GEMM_SMEM);
    cudaFuncSetAttribute((const void*)mamba_fused,              cudaFuncAttributeMaxDynamicSharedMemorySize, MAMBA_SMEM);

    // ---- weight-chain fusion prep ----
    // w21t[384,512] = ((expand@proj_in))^T, zero-padded rows
    { dim3 g((CEXP+31)/32, NPF/8);
      wmul_t_kernel<<<g, 256>>>(expand_w, proj_in_w, w21t, CEXP, C_, C_, NPF); }
    // in_proj -> bf16 [2432,512]
    wconv_kernel<<<(NP2320*CEXP + 255)/256, 256>>>(in_proj_w, wibf, D_IN_PROJ, CEXP, NP2320);
    // Wi_all[2432,320] = wibf @ w21t^T   (HMMA)
    { dim3 g(NPF/128, NP2320/128);
      tc_gemm<__nv_bfloat16,0><<<g, 256, GEMM_SMEM>>>(wibf, w21t, nullptr, wiall, NP2320, C_, CEXP); }
    // b21 = expand@proj_in_b + expand_b ; bi = in_proj@b21
    bfold_kernel<<<CEXP/8, 256>>>(expand_w, proj_in_b, expand_b, b21, CEXP, C_);
    bfold_kernel<<<(D_IN_PROJ+7)/8, 256>>>(in_proj_w, b21, nullptr, bi, D_IN_PROJ, CEXP);
    // wf1[384,512] = proj_out@collapse (zero-padded rows)
    { dim3 g((CEXP+31)/32, NPF/8);
      wmul_kernel<<<g, 256>>>(proj_out_w, collapse_w, wf1, C_, CEXP, C_, NPF); }
    // opT[1024,512] = out_proj^T * rms
    { dim3 g(CEXP/32, D_INNER/32);
      op_t_kernel<<<g, 256>>>(out_proj_w, rms_w, opt); }
    // Wf_all[384,1024] = wf1 @ opT^T   (HMMA)
    { dim3 g(D_INNER/128, NPF/128);
      tc_gemm<__nv_bfloat16,0><<<g, 256, GEMM_SMEM>>>(wf1, opt, nullptr, wfall, NPF, D_INNER, CEXP); }
    // bfin = proj_out@collapse_b + proj_out_b
    bfold_kernel<<<C_/8, 256>>>(proj_out_w, collapse_b, proj_out_b, bfin, C_, C_);

    // ---- main pipeline ----
    gn_stats<<<NFRM*GROUPS, 256>>>(x, gst);
    { dim3 g(C_/32, HW/32, NFRM); gn_apply<<<g, 256>>>(x, gst, norm_w, norm_b, a0); }

    // front GEMM: zx[NTOK,2320] = perm(a0) @ Wi_all^T + bi
    { dim3 g(NP2320/128, NTOK/128);
      tc_gemm<__nv_bfloat16,1><<<g, 256, GEMM_SMEM>>>(a0, wiall, bi, zxb, NTOK, D_IN_PROJ, C_); }

    // fused dt+conv+SSM+gate+RMSNorm -> unit-RMS bf16 y
    mamba_fused<<<NSEQ, 512, MAMBA_SMEM>>>(zxb, conv_w, conv_b, dt_bias, A_log, Dv, yb);

    // back GEMM: c2[NTOK,320] = perm(y) @ Wf_all^T + bfin (fp32 out)
    { dim3 g(NPF/128, NTOK/128);
      tc_gemm<float,2><<<g, 256, GEMM_SMEM>>>(yb, wfall, bfin, c2, NTOK, C_, D_INNER); }

    // residual + transpose
    { dim3 g(C_/32, HW/32, NFRM); final_t<<<g, 256>>>(x, c2, gamma, (float*)d_out); }
}

// round 9
// speedup vs baseline: 1.4518x; 1.3582x over previous
#include <cuda_runtime.h>
#include <cuda_bf16.h>
#include <math.h>
#include <cstdint>

#define B_      2
#define F_      16
#define H_      32
#define W_      32
#define HW      1024
#define NFRM    32
#define C_      320
#define CEXP    512
#define D_INNER 1024
#define NHEADS  16
#define HEADDIM 64
#define D_STATE 128
#define D_CONV  4
#define CONV_DIM 1280
#define D_IN_PROJ 2320
#define GROUPS  32
#define NSEQ    2048
#define L_      16
#define NTOK    32768

#define NP2320  2432
#define NPF     384

// ---------------- scratch ---------------------------------------------------
__device__ __nv_bfloat16 g_a0[(size_t)NTOK*C_];
__device__ __nv_bfloat16 g_zxb[(size_t)NTOK*D_IN_PROJ];
__device__ __nv_bfloat16 g_yb[(size_t)NTOK*D_INNER];
__device__ float         g_gst[NFRM*GROUPS*2];
__device__ __nv_bfloat16 g_w21t[NPF*CEXP];
__device__ __nv_bfloat16 g_wibf[(size_t)NP2320*CEXP];
__device__ __nv_bfloat16 g_wiall[(size_t)NP2320*C_];
__device__ __nv_bfloat16 g_wf1[NPF*CEXP];
__device__ __nv_bfloat16 g_opt[(size_t)D_INNER*CEXP];
__device__ __nv_bfloat16 g_wfall[(size_t)NPF*D_INNER];
__device__ float         g_b21[CEXP];
__device__ float         g_bi[D_IN_PROJ];
__device__ float         g_bf[C_];

// ---------------- PTX helpers ----------------------------------------------
__device__ __forceinline__ uint32_t smem_u32(const void* p) {
    uint32_t a;
    asm("{ .reg .u64 t; cvta.to.shared.u64 t, %1; cvt.u32.u64 %0, t; }" : "=r"(a) : "l"(p));
    return a;
}
__device__ __forceinline__ void cp16(uint32_t dst, const void* src) {
    asm volatile("cp.async.cg.shared.global [%0], [%1], 16;" :: "r"(dst), "l"(src) : "memory");
}
__device__ __forceinline__ void ldmx4(uint32_t addr, uint32_t& r0, uint32_t& r1,
                                      uint32_t& r2, uint32_t& r3) {
    asm volatile("ldmatrix.sync.aligned.m8n8.x4.shared.b16 {%0,%1,%2,%3}, [%4];"
                 : "=r"(r0), "=r"(r1), "=r"(r2), "=r"(r3) : "r"(addr));
}
__device__ __forceinline__ void mma16816(float* c, const uint32_t* a, const uint32_t* b) {
    asm volatile("mma.sync.aligned.m16n8k16.row.col.f32.bf16.bf16.f32 "
                 "{%0,%1,%2,%3}, {%4,%5,%6,%7}, {%8,%9}, {%0,%1,%2,%3};"
                 : "+f"(c[0]), "+f"(c[1]), "+f"(c[2]), "+f"(c[3])
                 : "r"(a[0]), "r"(a[1]), "r"(a[2]), "r"(a[3]), "r"(b[0]), "r"(b[1]));
}
__device__ __forceinline__ void storev2(float* p, float v0, float v1) { p[0] = v0; p[1] = v1; }
__device__ __forceinline__ void storev2(__nv_bfloat16* p, float v0, float v1) {
    __nv_bfloat162 t;
    t.x = __float2bfloat16(v0); t.y = __float2bfloat16(v1);
    *reinterpret_cast<__nv_bfloat162*>(p) = t;
}

// row remap for fused permutes
template<int PERM> __device__ __forceinline__ int rowmap(int r) {
    if (PERM == 1) {            // dest seq-order, src frame-order
        int f = r & 15, hw = (r >> 4) & 1023, bb = r >> 14;
        return bb * 16384 + f * 1024 + hw;
    } else if (PERM == 2) {     // dest frame-order, src seq-order
        int hw = r & 1023, f = (r >> 10) & 15, bb = r >> 14;
        return bb * 16384 + hw * 16 + f;
    }
    return r;
}

// ---------------- bf16 HMMA GEMM (128x128x64, 3-stage) -----------------------
#define GEMM_SMEM (3*2*18432)   // 110592
template<typename OutT, int PERM>
__global__ void __launch_bounds__(256, 2)
tc_gemm(const __nv_bfloat16* __restrict__ A, const __nv_bfloat16* __restrict__ B,
        const float* __restrict__ bias, OutT* __restrict__ C, int M, int N, int K)
{
    extern __shared__ char smraw[];
    const uint32_t sbase = smem_u32(smraw);
    const int tid = threadIdx.x;
    const int lane = tid & 31, warp = tid >> 5;
    const int wm = (warp & 3) * 32, wn = (warp >> 2) * 64;
    const int m0 = blockIdx.y * 128, n0 = blockIdx.x * 128;

    const int seg = tid & 7, r0 = tid >> 3;
    int arows[4];
    #pragma unroll
    for (int j = 0; j < 4; ++j) arows[j] = rowmap<PERM>(m0 + r0 + j * 32);

    float acc[2][8][4];
    #pragma unroll
    for (int i = 0; i < 2; ++i)
        #pragma unroll
        for (int j = 0; j < 8; ++j)
            #pragma unroll
            for (int k = 0; k < 4; ++k) acc[i][j][k] = 0.f;

    const int nc = K >> 6;
    auto load = [&](int i) {
        const uint32_t da = sbase + (uint32_t)(i % 3) * 36864u;
        const uint32_t db = da + 18432u;
        const int k0 = i << 6;
        #pragma unroll
        for (int j = 0; j < 4; ++j) {
            int row = r0 + j * 32;
            uint32_t off = (uint32_t)row * 144u + (uint32_t)seg * 16u;
            cp16(da + off, A + (size_t)arows[j] * K + k0 + seg * 8);
            cp16(db + off, B + (size_t)(n0 + row) * K + k0 + seg * 8);
        }
        asm volatile("cp.async.commit_group;" ::: "memory");
    };

    load(0);
    if (nc > 1) load(1);

    for (int i = 0; i < nc; ++i) {
        if (i + 1 < nc) asm volatile("cp.async.wait_group 1;" ::: "memory");
        else            asm volatile("cp.async.wait_group 0;" ::: "memory");
        __syncthreads();
        if (i + 2 < nc) load(i + 2);

        const uint32_t sA  = sbase + (uint32_t)(i % 3) * 36864u;
        const uint32_t sBt = sA + 18432u;
        #pragma unroll
        for (int ks = 0; ks < 64; ks += 16) {
            uint32_t af[2][4];
            #pragma unroll
            for (int mt = 0; mt < 2; ++mt) {
                uint32_t addr = sA
                    + (uint32_t)(wm + mt * 16 + (lane & 15)) * 144u
                    + (uint32_t)(ks + ((lane >> 4) << 3)) * 2u;
                ldmx4(addr, af[mt][0], af[mt][1], af[mt][2], af[mt][3]);
            }
            uint32_t bf[8][2];
            #pragma unroll
            for (int nt2 = 0; nt2 < 4; ++nt2) {
                int n  = wn + nt2 * 16 + (lane & 7) + ((lane >> 4) << 3);
                int kk = ks + (((lane >> 3) & 1) << 3);
                uint32_t addr = sBt + (uint32_t)n * 144u + (uint32_t)kk * 2u;
                ldmx4(addr, bf[nt2*2][0], bf[nt2*2][1], bf[nt2*2+1][0], bf[nt2*2+1][1]);
            }
            #pragma unroll
            for (int mt = 0; mt < 2; ++mt)
                #pragma unroll
                for (int nt = 0; nt < 8; ++nt)
                    mma16816(acc[mt][nt], af[mt], bf[nt]);
        }
    }

    #pragma unroll
    for (int mt = 0; mt < 2; ++mt) {
        int row = m0 + wm + mt * 16 + (lane >> 2);
        #pragma unroll
        for (int nt = 0; nt < 8; ++nt) {
            int col = n0 + wn + nt * 8 + (lane & 3) * 2;
            if (col < N) {
                float b0 = bias ? bias[col]     : 0.f;
                float b1 = bias ? bias[col + 1] : 0.f;
                storev2(C + (size_t)row * N + col,       acc[mt][nt][0] + b0, acc[mt][nt][1] + b1);
                storev2(C + (size_t)(row + 8) * N + col, acc[mt][nt][2] + b0, acc[mt][nt][3] + b1);
            }
        }
    }
}

// ---------------- back GEMM: out = x + gamma*(perm(y)@Wf^T + bias), fused ----
// PERM=2 A rows; 128-token tiles share one frame n; smem-transpose epilogue.
__global__ void __launch_bounds__(256, 2)
tc_gemm_back(const __nv_bfloat16* __restrict__ A, const __nv_bfloat16* __restrict__ B,
             const float* __restrict__ bias, const float* __restrict__ x,
             const float* __restrict__ gamma, float* __restrict__ out, int K)
{
    extern __shared__ char smraw[];
    const uint32_t sbase = smem_u32(smraw);
    const int tid = threadIdx.x;
    const int lane = tid & 31, warp = tid >> 5;
    const int wm = (warp & 3) * 32, wn = (warp >> 2) * 64;
    const int m0 = blockIdx.y * 128, n0 = blockIdx.x * 128;

    const int seg = tid & 7, r0 = tid >> 3;
    int arows[4];
    #pragma unroll
    for (int j = 0; j < 4; ++j) arows[j] = rowmap<2>(m0 + r0 + j * 32);

    float acc[2][8][4];
    #pragma unroll
    for (int i = 0; i < 2; ++i)
        #pragma unroll
        for (int j = 0; j < 8; ++j)
            #pragma unroll
            for (int k = 0; k < 4; ++k) acc[i][j][k] = 0.f;

    const int nc = K >> 6;
    auto load = [&](int i) {
        const uint32_t da = sbase + (uint32_t)(i % 3) * 36864u;
        const uint32_t db = da + 18432u;
        const int k0 = i << 6;
        #pragma unroll
        for (int j = 0; j < 4; ++j) {
            int row = r0 + j * 32;
            uint32_t off = (uint32_t)row * 144u + (uint32_t)seg * 16u;
            cp16(da + off, A + (size_t)arows[j] * K + k0 + seg * 8);
            cp16(db + off, B + (size_t)(n0 + row) * K + k0 + seg * 8);
        }
        asm volatile("cp.async.commit_group;" ::: "memory");
    };

    load(0);
    if (nc > 1) load(1);

    for (int i = 0; i < nc; ++i) {
        if (i + 1 < nc) asm volatile("cp.async.wait_group 1;" ::: "memory");
        else            asm volatile("cp.async.wait_group 0;" ::: "memory");
        __syncthreads();
        if (i + 2 < nc) load(i + 2);

        const uint32_t sA  = sbase + (uint32_t)(i % 3) * 36864u;
        const uint32_t sBt = sA + 18432u;
        #pragma unroll
        for (int ks = 0; ks < 64; ks += 16) {
            uint32_t af[2][4];
            #pragma unroll
            for (int mt = 0; mt < 2; ++mt) {
                uint32_t addr = sA
                    + (uint32_t)(wm + mt * 16 + (lane & 15)) * 144u
                    + (uint32_t)(ks + ((lane >> 4) << 3)) * 2u;
                ldmx4(addr, af[mt][0], af[mt][1], af[mt][2], af[mt][3]);
            }
            uint32_t bf[8][2];
            #pragma unroll
            for (int nt2 = 0; nt2 < 4; ++nt2) {
                int n  = wn + nt2 * 16 + (lane & 7) + ((lane >> 4) << 3);
                int kk = ks + (((lane >> 3) & 1) << 3);
                uint32_t addr = sBt + (uint32_t)n * 144u + (uint32_t)kk * 2u;
                ldmx4(addr, bf[nt2*2][0], bf[nt2*2][1], bf[nt2*2+1][0], bf[nt2*2+1][1]);
            }
            #pragma unroll
            for (int mt = 0; mt < 2; ++mt)
                #pragma unroll
                for (int nt = 0; nt < 8; ++nt)
                    mma16816(acc[mt][nt], af[mt], bf[nt]);
        }
    }
    __syncthreads();   // all smem reads done; reuse ring as transpose tile

    float* tile = (float*)smraw;    // [128][129]
    #pragma unroll
    for (int mt = 0; mt < 2; ++mt) {
        int r = wm + mt * 16 + (lane >> 2);
        #pragma unroll
        for (int nt = 0; nt < 8; ++nt) {
            int cA = wn + nt * 8 + (lane & 3) * 2;
            int col = n0 + cA;
            float b0 = (col < C_)     ? bias[col]     : 0.f;
            float b1 = (col + 1 < C_) ? bias[col + 1] : 0.f;
            tile[cA * 129 + r]           = acc[mt][nt][0] + b0;
            tile[(cA + 1) * 129 + r]     = acc[mt][nt][1] + b1;
            tile[cA * 129 + r + 8]       = acc[mt][nt][2] + b0;
            tile[(cA + 1) * 129 + r + 8] = acc[mt][nt][3] + b1;
        }
    }
    __syncthreads();

    const int n = m0 >> 10, hw0 = m0 & 1023;
    const float gm = gamma[0];
    for (int i = tid; i < 128 * 128; i += 256) {
        int cc = i >> 7, hh = i & 127;
        int c = n0 + cc;
        if (c < C_) {
            size_t idx = ((size_t)n * C_ + c) * HW + hw0 + hh;
            out[idx] = x[idx] + gm * tile[cc * 129 + hh];
        }
    }
}

// ---------------- fused prep: gn_stats | w21t | wibf -------------------------
__global__ void fused_prep(const float* __restrict__ x, float* __restrict__ st,
                           const float* __restrict__ expand_w, const float* __restrict__ proj_in_w,
                           __nv_bfloat16* __restrict__ w21t,
                           const float* __restrict__ in_proj_w, __nv_bfloat16* __restrict__ wibf)
{
    const int z = blockIdx.z, bx = blockIdx.x, tid = threadIdx.x;
    if (z == 0) {
        if (bx >= NFRM * GROUPS) return;
        int n = bx >> 5, g = bx & 31;
        const int CPG = C_ / GROUPS;
        const float* base = x + ((size_t)n * C_ + g * CPG) * HW;
        float s = 0.f, ss = 0.f;
        for (int i = tid; i < CPG * HW; i += 256) { float v = base[i]; s += v; ss += v * v; }
        __shared__ float rs[256], rq[256];
        rs[tid] = s; rq[tid] = ss; __syncthreads();
        for (int o = 128; o > 0; o >>= 1) {
            if (tid < o) { rs[tid] += rs[tid + o]; rq[tid] += rq[tid + o]; }
            __syncthreads();
        }
        if (tid == 0) {
            float mean = rs[0] / (CPG * HW);
            float var  = rq[0] / (CPG * HW) - mean * mean;
            st[bx * 2]     = mean;
            st[bx * 2 + 1] = rsqrtf(var + 1e-5f);
        }
    } else if (z == 1) {
        if (bx >= 16 * 48) return;
        int lane = tid & 31, w = tid >> 5;
        int m = (bx & 15) * 32 + lane;          // < 512
        int r = (bx >> 4) * 8 + w;              // < 384
        float s = 0.f;
        if (r < C_) {
            const float* ar = expand_w + (size_t)m * C_;
            const float* bc = proj_in_w + r;
            for (int k = 0; k < C_; ++k) s += ar[k] * bc[(size_t)k * C_];
        }
        w21t[(size_t)r * CEXP + m] = __float2bfloat16(s);
    } else {
        int idx = bx * 256 + tid;               // exactly NP2320*CEXP
        wibf[idx] = __float2bfloat16(idx < D_IN_PROJ * CEXP ? in_proj_w[idx] : 0.f);
    }
}

// ---------------- other prep -------------------------------------------------
__global__ void wmul_kernel(const float* __restrict__ A, const float* __restrict__ B,
                            __nv_bfloat16* __restrict__ C, int M, int N, int K, int Mpad)
{
    int lane = threadIdx.x & 31, w = threadIdx.x >> 5;
    int m = blockIdx.y * 8 + w;
    int n = blockIdx.x * 32 + lane;
    if (m >= Mpad || n >= N) return;
    float s = 0.f;
    if (m < M) {
        const float* ar = A + (size_t)m * K;
        const float* bc = B + n;
        for (int k = 0; k < K; ++k) s += ar[k] * bc[(size_t)k * N];
    }
    C[(size_t)m * N + n] = __float2bfloat16(s);
}
__global__ void bfold_kernel(const float* __restrict__ W, const float* __restrict__ bin,
                             const float* __restrict__ badd, float* __restrict__ bout,
                             int N, int K) {
    int lane = threadIdx.x & 31, w = threadIdx.x >> 5;
    int n = blockIdx.x * 8 + w;
    if (n >= N) return;
    float s = 0.f;
    for (int k = lane; k < K; k += 32) s += W[(size_t)n * K + k] * bin[k];
    #pragma unroll
    for (int off = 16; off > 0; off >>= 1) s += __shfl_xor_sync(0xffffffffu, s, off);
    if (lane == 0) bout[n] = s + (badd ? badd[n] : 0.f);
}
__global__ void op_t_kernel(const float* __restrict__ W, const float* __restrict__ rms,
                            __nv_bfloat16* __restrict__ o) {
    __shared__ float t[32][33];
    int o0 = blockIdx.x * 32, d0 = blockIdx.y * 32;
    int tx = threadIdx.x & 31, ty = threadIdx.x >> 5;
    #pragma unroll
    for (int r = 0; r < 4; ++r)
        t[ty + r * 8][tx] = W[(size_t)(o0 + ty + r * 8) * D_INNER + d0 + tx];
    __syncthreads();
    #pragma unroll
    for (int r = 0; r < 4; ++r) {
        int d = d0 + ty + r * 8;
        o[(size_t)d * CEXP + o0 + tx] = __float2bfloat16(t[tx][ty + r * 8] * rms[d]);
    }
}

// ---------------- GroupNorm apply --------------------------------------------
__global__ void gn_apply(const float* __restrict__ x, const float* __restrict__ st,
                         const float* __restrict__ w, const float* __restrict__ b,
                         __nv_bfloat16* __restrict__ out) {
    __shared__ float tile[32][33];
    int c0 = blockIdx.x * 32, hw0 = blockIdx.y * 32, n = blockIdx.z;
    int tx = threadIdx.x & 31, ty = threadIdx.x >> 5;
    #pragma unroll
    for (int r = 0; r < 4; ++r) {
        int c = c0 + ty + r * 8;
        int g = c / 10;
        float mean = st[(n * 32 + g) * 2], inv = st[(n * 32 + g) * 2 + 1];
        float v = x[((size_t)n * C_ + c) * HW + hw0 + tx];
        tile[ty + r * 8][tx] = (v - mean) * inv * w[c] + b[c];
    }
    __syncthreads();
    #pragma unroll
    for (int r = 0; r < 4; ++r) {
        int hw = hw0 + ty + r * 8;
        out[((size_t)n * HW + hw) * C_ + c0 + tx] = __float2bfloat16(tile[tx][ty + r * 8]);
    }
}

// ---------------- fused dt + conv + SSM + gate + RMSNorm ---------------------
// bi bias applied here; bf16 smem -> 2 CTAs/SM; emits unit-RMS bf16 y.
#define CDP 1282
#define MAMBA_SMEM 93312
__global__ void __launch_bounds__(512)
mamba_fused(const __nv_bfloat16* __restrict__ zx, const float* __restrict__ bi,
            const float* __restrict__ cw, const float* __restrict__ cb,
            const float* __restrict__ dt_bias, const float* __restrict__ A_log,
            const float* __restrict__ Dv, __nv_bfloat16* __restrict__ yb)
{
    extern __shared__ char sm[];
    __nv_bfloat16* sx = (__nv_bfloat16*)sm;                 // [16][1282] bf16
    __nv_bfloat16* sy = (__nv_bfloat16*)(sm + 41024);       // [16][1024] bf16
    float* sW     = (float*)(sm + 73792);                   // [16][16][16]
    float* sScore = (float*)(sm + 90176);
    float* sDt    = (float*)(sm + 91200);
    float* sCum   = (float*)(sm + 92224);
    float* sSq    = (float*)(sm + 93248);
    const int s = blockIdx.x, tid = threadIdx.x;
    const __nv_bfloat16* zb = zx + (size_t)s * L_ * D_IN_PROJ;

    if (tid < 256) {
        int l = tid >> 4, h = tid & 15;
        float v = __bfloat162float(zb[(size_t)l * D_IN_PROJ + 2304 + h]) + bi[2304 + h] + dt_bias[h];
        sDt[l * 16 + h] = (v > 20.f) ? v : log1pf(expf(v));
    }
    if (tid < 16) sSq[tid] = 0.f;

    for (int c = tid; c < CONV_DIM; c += 512) {
        float w0 = cw[c*4], w1 = cw[c*4+1], w2 = cw[c*4+2], w3 = cw[c*4+3];
        float bb = cb[c];
        float bic = bi[D_INNER + c];
        float v0 = 0.f, v1 = 0.f, v2 = 0.f;
        const __nv_bfloat16* base = zb + D_INNER + c;
        #pragma unroll
        for (int l = 0; l < L_; ++l) {
            float v3 = __bfloat162float(base[(size_t)l * D_IN_PROJ]) + bic;
            float o = v0*w0 + v1*w1 + v2*w2 + v3*w3 + bb;
            o = o / (1.f + expf(-o));
            sx[l * CDP + c] = __float2bfloat16(o);
            v0 = v1; v1 = v2; v2 = v3;
        }
    }
    __syncthreads();

    if (tid < 256) {
        int l = tid >> 4, sp = tid & 15;
        float acc = 0.f;
        #pragma unroll 8
        for (int n = 0; n < D_STATE; ++n)
            acc += __bfloat162float(sx[l * CDP + D_INNER + D_STATE + n])
                 * __bfloat162float(sx[sp * CDP + D_INNER + n]);
        sScore[l * 16 + sp] = acc;
    } else if (tid < 272) {
        int h = tid - 256;
        float a = -expf(A_log[h]);
        float run = 0.f;
        #pragma unroll
        for (int l = 0; l < L_; ++l) { run += sDt[l * 16 + h] * a; sCum[l * 16 + h] = run; }
    }
    __syncthreads();

    for (int i = tid; i < NHEADS * 256; i += 512) {
        int h = i >> 8, l = (i >> 4) & 15, sp = i & 15;
        float w;
        if (sp < l)       w = sScore[l*16+sp] * expf(sCum[l*16+h] - sCum[sp*16+h]) * sDt[sp*16+h];
        else if (sp == l) w = sScore[l*16+l] * sDt[l*16+h] + Dv[h];
        else              w = 0.f;
        sW[(h * 16 + l) * 16 + sp] = w;
    }
    __syncthreads();

    const int h = tid >> 5, lane = tid & 31;
    const float bz0 = bi[h * HEADDIM + lane];
    const float bz1 = bi[h * HEADDIM + lane + 32];
    float x0[L_], x1[L_];
    #pragma unroll
    for (int sp = 0; sp < L_; ++sp) {
        x0[sp] = __bfloat162float(sx[sp * CDP + h * HEADDIM + lane]);
        x1[sp] = __bfloat162float(sx[sp * CDP + h * HEADDIM + lane + 32]);
    }
    #pragma unroll
    for (int l = 0; l < L_; ++l) {
        float a0 = 0.f, a1 = 0.f;
        for (int sp = 0; sp <= l; ++sp) {
            float w = sW[(h * 16 + l) * 16 + sp];
            a0 += w * x0[sp]; a1 += w * x1[sp];
        }
        float z0 = __bfloat162float(zb[(size_t)l * D_IN_PROJ + h * HEADDIM + lane]) + bz0;
        float z1 = __bfloat162float(zb[(size_t)l * D_IN_PROJ + h * HEADDIM + lane + 32]) + bz1;
        a0 *= z0 / (1.f + expf(-z0));
        a1 *= z1 / (1.f + expf(-z1));
        sy[l * 1024 + h * HEADDIM + lane]      = __float2bfloat16(a0);
        sy[l * 1024 + h * HEADDIM + lane + 32] = __float2bfloat16(a1);
        float q = a0 * a0 + a1 * a1;
        #pragma unroll
        for (int off = 16; off > 0; off >>= 1) q += __shfl_xor_sync(0xffffffffu, q, off);
        if (lane == 0) atomicAdd(&sSq[l], q);
    }
    __syncthreads();
    if (tid < 16) sSq[tid] = rsqrtf(sSq[tid] / (float)D_INNER + 1e-5f);
    __syncthreads();

    __nv_bfloat16* ob = yb + (size_t)s * L_ * D_INNER;
    for (int i = tid; i < L_ * D_INNER; i += 512) {
        int l = i >> 10;
        ob[i] = __float2bfloat16(__bfloat162float(sy[i]) * sSq[l]);
    }
}

// ---------------- launch -------------------------------------------------------
extern "C" void kernel_launch(void* const* d_in, const int* in_sizes, int n_in,
                              void* d_out, int out_size) {
    const float* x          = (const float*)d_in[0];
    const float* norm_w     = (const float*)d_in[1];
    const float* norm_b     = (const float*)d_in[2];
    const float* proj_in_w  = (const float*)d_in[3];
    const float* proj_in_b  = (const float*)d_in[4];
    const float* expand_w   = (const float*)d_in[5];
    const float* expand_b   = (const float*)d_in[6];
    const float* in_proj_w  = (const float*)d_in[7];
    const float* conv_w     = (const float*)d_in[8];
    const float* conv_b     = (const float*)d_in[9];
    const float* dt_bias    = (const float*)d_in[10];
    const float* A_log      = (const float*)d_in[11];
    const float* Dv         = (const float*)d_in[12];
    const float* rms_w      = (const float*)d_in[13];
    const float* out_proj_w = (const float*)d_in[14];
    const float* collapse_w = (const float*)d_in[15];
    const float* collapse_b = (const float*)d_in[16];
    const float* proj_out_w = (const float*)d_in[17];
    const float* proj_out_b = (const float*)d_in[18];
    const float* gamma      = (const float*)d_in[19];

    __nv_bfloat16 *a0, *zxb, *yb, *w21t, *wibf, *wiall, *wf1, *opt, *wfall;
    float *gst, *b21, *bi, *bfin;
    cudaGetSymbolAddress((void**)&a0,   g_a0);   cudaGetSymbolAddress((void**)&zxb,  g_zxb);
    cudaGetSymbolAddress((void**)&yb,   g_yb);   cudaGetSymbolAddress((void**)&gst,  g_gst);
    cudaGetSymbolAddress((void**)&w21t, g_w21t); cudaGetSymbolAddress((void**)&wibf, g_wibf);
    cudaGetSymbolAddress((void**)&wiall,g_wiall);cudaGetSymbolAddress((void**)&wf1,  g_wf1);
    cudaGetSymbolAddress((void**)&opt,  g_opt);  cudaGetSymbolAddress((void**)&wfall,g_wfall);
    cudaGetSymbolAddress((void**)&b21,  g_b21);  cudaGetSymbolAddress((void**)&bi,   g_bi);
    cudaGetSymbolAddress((void**)&bfin, g_bf);

    cudaFuncSetAttribute((const void*)tc_gemm<__nv_bfloat16,0>, cudaFuncAttributeMaxDynamicSharedMemorySize, GEMM_SMEM);
    cudaFuncSetAttribute((const void*)tc_gemm<__nv_bfloat16,1>, cudaFuncAttributeMaxDynamicSharedMemorySize, GEMM_SMEM);
    cudaFuncSetAttribute((const void*)tc_gemm_back,             cudaFuncAttributeMaxDynamicSharedMemorySize, GEMM_SMEM);
    cudaFuncSetAttribute((const void*)mamba_fused,              cudaFuncAttributeMaxDynamicSharedMemorySize, MAMBA_SMEM);

    // 1. fused prep: gn_stats | w21t | wibf
    { dim3 g(4864, 1, 3);
      fused_prep<<<g, 256>>>(x, gst, expand_w, proj_in_w, w21t, in_proj_w, wibf); }
    // 2. gn_apply -> a0
    { dim3 g(C_/32, HW/32, NFRM); gn_apply<<<g, 256>>>(x, gst, norm_w, norm_b, a0); }
    // 3. Wi_all = wibf @ w21t^T
    { dim3 g(NPF/128, NP2320/128);
      tc_gemm<__nv_bfloat16,0><<<g, 256, GEMM_SMEM>>>(wibf, w21t, nullptr, wiall, NP2320, C_, CEXP); }
    // 4. FRONT GEMM (profiled): zx = perm(a0) @ Wi_all^T
    { dim3 g(NP2320/128, NTOK/128);
      tc_gemm<__nv_bfloat16,1><<<g, 256, GEMM_SMEM>>>(a0, wiall, nullptr, zxb, NTOK, D_IN_PROJ, C_); }
    // 5-6. bias chain: b21 then bi
    bfold_kernel<<<CEXP/8, 256>>>(expand_w, proj_in_b, expand_b, b21, CEXP, C_);
    bfold_kernel<<<(D_IN_PROJ+7)/8, 256>>>(in_proj_w, b21, nullptr, bi, D_IN_PROJ, CEXP);
    // 7. fused mamba (applies bi)
    mamba_fused<<<NSEQ, 512, MAMBA_SMEM>>>(zxb, bi, conv_w, conv_b, dt_bias, A_log, Dv, yb);
    // 8-11. back-weight prep
    { dim3 g((CEXP+31)/32, NPF/8);
      wmul_kernel<<<g, 256>>>(proj_out_w, collapse_w, wf1, C_, CEXP, C_, NPF); }
    { dim3 g(CEXP/32, D_INNER/32);
      op_t_kernel<<<g, 256>>>(out_proj_w, rms_w, opt); }
    { dim3 g(D_INNER/128, NPF/128);
      tc_gemm<__nv_bfloat16,0><<<g, 256, GEMM_SMEM>>>(wf1, opt, nullptr, wfall, NPF, D_INNER, CEXP); }
    bfold_kernel<<<C_/8, 256>>>(proj_out_w, collapse_b, proj_out_b, bfin, C_, C_);
    // 12. BACK GEMM fused with residual+transpose -> d_out
    { dim3 g(NPF/128, NTOK/128);
      tc_gemm_back<<<g, 256, GEMM_SMEM>>>(yb, wfall, bfin, x, gamma, (float*)d_out, D_INNER); }
}